// round 13
// baseline (speedup 1.0000x reference)
#include <cuda_runtime.h>
#include <cuda_bf16.h>
#include <cuda_fp16.h>
#include <math.h>
#include <stdint.h>

// ---------------- problem constants ----------------
#define NB       512
#define PP       64
#define NN       (NB*PP)      // 32768
#define FF       128
#define HH       256
#define KSORT    30
#define LOUT     27
#define MCONV    (NB*LOUT)    // 13824

// ---------------- static scratch ----------------
__device__ __align__(16) float g_A  [NB*PP*PP];
__device__ __align__(16) float g_H  [NN*HH];      // fp32 activations (sort keys)
__device__ __align__(16) float g_HL [NN*HH];
__device__ __align__(16) float g_HR [NN*HH];
__device__ __align__(16) float g_z1 [NB*HH];
// fp16 2-plane activations ping/pong
__device__ __align__(16) __half g_a0[NN*HH], g_a1[NN*HH];
__device__ __align__(16) __half g_b0[NN*HH], g_b1[NN*HH];
// fp16 sage weight planes [8 mats][256][K]
__device__ __align__(16) __half g_w0[8*HH*HH], g_w1[8*HH*HH];
// conv path (bf16 2-plane)
__device__ __align__(16) __nv_bfloat16 g_t0[NB*KSORT*HH], g_t1[NB*KSORT*HH];
__device__ __align__(16) __nv_bfloat16 g_c0[HH*1024],     g_c1[HH*1024];
// conv output as bf16 split-2 planes [(g,tp)][o]
__device__ __align__(16) __nv_bfloat16 g_y0[MCONV*HH], g_y1[MCONV*HH];
// lin1 weight planes [ts][n][o]
__device__ __align__(16) __nv_bfloat16 g_l0[LOUT*HH*HH], g_l1[LOUT*HH*HH];

// ---------------- helpers ----------------
__device__ __forceinline__ uint32_t smem_u32(const void* p) {
    uint32_t a;
    asm("{ .reg .u64 t; cvta.to.shared.u64 t, %1; cvt.u32.u64 %0, t; }" : "=r"(a) : "l"(p));
    return a;
}
__device__ __forceinline__ void cpasync16(uint32_t dst, const void* src) {
    asm volatile("cp.async.cg.shared.global [%0], [%1], 16;" :: "r"(dst), "l"(src));
}
__device__ __forceinline__ void ldsm4(uint32_t* r, uint32_t addr) {
    asm volatile("ldmatrix.sync.aligned.m8n8.x4.shared.b16 {%0,%1,%2,%3}, [%4];"
        : "=r"(r[0]), "=r"(r[1]), "=r"(r[2]), "=r"(r[3]) : "r"(addr));
}
__device__ __forceinline__ void mma16bf(float* d, uint32_t a0, uint32_t a1,
                                        uint32_t a2, uint32_t a3,
                                        uint32_t b0, uint32_t b1) {
    asm volatile(
        "mma.sync.aligned.m16n8k16.row.col.f32.bf16.bf16.f32 "
        "{%0,%1,%2,%3}, {%4,%5,%6,%7}, {%8,%9}, {%0,%1,%2,%3};"
        : "+f"(d[0]), "+f"(d[1]), "+f"(d[2]), "+f"(d[3])
        : "r"(a0), "r"(a1), "r"(a2), "r"(a3), "r"(b0), "r"(b1));
}
__device__ __forceinline__ void mma16h(float* d, const uint32_t* a,
                                       uint32_t b0, uint32_t b1) {
    asm volatile(
        "mma.sync.aligned.m16n8k16.row.col.f32.f16.f16.f32 "
        "{%0,%1,%2,%3}, {%4,%5,%6,%7}, {%8,%9}, {%0,%1,%2,%3};"
        : "+f"(d[0]), "+f"(d[1]), "+f"(d[2]), "+f"(d[3])
        : "r"(a[0]), "r"(a[1]), "r"(a[2]), "r"(a[3]), "r"(b0), "r"(b1));
}
struct H2S { __half x, y; };
__device__ __forceinline__ H2S h2_split(float v) {
    H2S r;
    r.x = __float2half_rn(v);
    float rem = v - __half2float(r.x);
    r.y = __float2half_rn(rem);
    return r;
}
__device__ __forceinline__ __nv_bfloat162 bf2_split(float v) {
    __nv_bfloat16 h0 = __float2bfloat16(v);
    __nv_bfloat16 h1 = __float2bfloat16(v - __bfloat162float(h0));
    __nv_bfloat162 r; r.x = h0; r.y = h1; return r;
}

// ===== SAGE GEMM: fp16 2-plane 3-product split-acc; jp-merged passes ========
// Bit-identical to R11/R12: per-accumulator MMA chain order unchanged (per
// output: s ascending; hi += a0b0; lo += a0b1 then a1b0). Only cross-
// accumulator interleaving widened: 8 independent MMAs per pass.
#define GPROW_B   80
#define GA_PLANE  (128*GPROW_B)
#define GB_PLANE  (64*GPROW_B)
#define GSTAGE    (2*GA_PLANE + 2*GB_PLANE)
#define GSMZ      (3*GSTAGE)

__global__ __launch_bounds__(256, 2) void gemm_sage_tc(
    const __half* __restrict__ A0, const __half* __restrict__ A1,
    const __half* __restrict__ L0, const __half* __restrict__ L1,
    const __half* __restrict__ R0, const __half* __restrict__ R1,
    float* __restrict__ Cl, float* __restrict__ Cr, int K)
{
    extern __shared__ char smem[];
    const int t    = threadIdx.x;
    const int lane = t & 31;
    const int wid  = t >> 5;
    const int wm   = wid & 3;
    const int wn   = wid >> 2;
    const int m0   = blockIdx.y * 128;
    const int sel  = blockIdx.x >> 2;
    const int n0   = (blockIdx.x & 3) * 64;
    const int lr   = lane >> 2;
    const int lc   = lane & 3;
    const int nch  = K >> 5;

    const __half* W0 = sel ? R0 : L0;
    const __half* W1 = sel ? R1 : L1;
    float* C = sel ? Cr : Cl;

    uint32_t sbase = smem_u32(smem);

    const int l15    = lane & 15;
    const int koff_a = (lane >> 4) * 16;
    const int brow_l = ((lane >> 4) << 3) + (lane & 7);
    const int koff_b = ((lane >> 3) & 1) * 16;

    auto ld_stage = [&](int stage, int c) {
        uint32_t sb = sbase + stage * GSTAGE;
        int kt = c << 5;
        #pragma unroll
        for (int i = 0; i < 6; i++) {
            int idx = t + i * 256;
            if (idx < 1024) {
                int pl = idx >> 9, rem = idx & 511;
                int row = rem >> 2, q = rem & 3;
                const __half* P = pl ? A1 : A0;
                cpasync16(sb + pl * GA_PLANE + row * GPROW_B + q * 16,
                          P + (size_t)(m0 + row) * K + kt + q * 8);
            } else {
                int idx2 = idx - 1024;
                int pl = idx2 >> 8, rem = idx2 & 255;
                int row = rem >> 2, q = rem & 3;
                const __half* P = pl ? W1 : W0;
                cpasync16(sb + 2 * GA_PLANE + pl * GB_PLANE + row * GPROW_B + q * 16,
                          P + (size_t)(n0 + row) * K + kt + q * 8);
            }
        }
        asm volatile("cp.async.commit_group;" ::: "memory");
    };

    float acc_hi[2][4][4], acc_lo[2][4][4];
    #pragma unroll
    for (int m = 0; m < 2; m++)
        #pragma unroll
        for (int j = 0; j < 4; j++)
            #pragma unroll
            for (int q = 0; q < 4; q++) { acc_hi[m][j][q] = 0.f; acc_lo[m][j][q] = 0.f; }

    ld_stage(0, 0);
    if (nch > 1) ld_stage(1, 1);

    int st = 0;
    for (int c = 0; c < nch; c++) {
        if (c + 1 < nch) asm volatile("cp.async.wait_group 1;" ::: "memory");
        else             asm volatile("cp.async.wait_group 0;" ::: "memory");
        __syncthreads();
        if (c + 2 < nch) {
            int st2 = st + 2; if (st2 >= 3) st2 -= 3;
            ld_stage(st2, c + 2);
        }

        uint32_t sb = sbase + st * GSTAGE;

        #pragma unroll
        for (int s = 0; s < 2; s++) {
            uint32_t a0f[2][4], a1f[2][4];
            #pragma unroll
            for (int m = 0; m < 2; m++) {
                uint32_t rowb = (uint32_t)((wm * 32 + m * 16 + l15) * GPROW_B
                                           + s * 32 + koff_a);
                ldsm4(a0f[m], sb + rowb);
                ldsm4(a1f[m], sb + GA_PLANE + rowb);
            }
            uint32_t b0[2][4], b1[2][4];
            #pragma unroll
            for (int jp = 0; jp < 2; jp++) {
                uint32_t nrow = sb + 2 * GA_PLANE
                    + (uint32_t)((wn * 32 + jp * 16 + brow_l) * GPROW_B
                                 + s * 32 + koff_b);
                ldsm4(b0[jp], nrow);
                ldsm4(b1[jp], nrow + GB_PLANE);
            }
            // pass 1: all 8 hi (a0*b0)
            #pragma unroll
            for (int jp = 0; jp < 2; jp++)
                #pragma unroll
                for (int jj = 0; jj < 2; jj++)
                    #pragma unroll
                    for (int m = 0; m < 2; m++)
                        mma16h(acc_hi[m][jp*2+jj], a0f[m], b0[jp][2*jj], b0[jp][2*jj+1]);
            // pass 2: all 8 lo (a0*b1)
            #pragma unroll
            for (int jp = 0; jp < 2; jp++)
                #pragma unroll
                for (int jj = 0; jj < 2; jj++)
                    #pragma unroll
                    for (int m = 0; m < 2; m++)
                        mma16h(acc_lo[m][jp*2+jj], a0f[m], b1[jp][2*jj], b1[jp][2*jj+1]);
            // pass 3: all 8 lo (a1*b0) — 8-slot same-acc gap from pass 2
            #pragma unroll
            for (int jp = 0; jp < 2; jp++)
                #pragma unroll
                for (int jj = 0; jj < 2; jj++)
                    #pragma unroll
                    for (int m = 0; m < 2; m++)
                        mma16h(acc_lo[m][jp*2+jj], a1f[m], b0[jp][2*jj], b0[jp][2*jj+1]);
        }
        if (++st == 3) st = 0;
    }

    #pragma unroll
    for (int m = 0; m < 2; m++) {
        int row = m0 + wm * 32 + m * 16 + lr;
        #pragma unroll
        for (int j = 0; j < 4; j++) {
            int col = n0 + wn * 32 + j * 8 + 2 * lc;
            float2 v0 = make_float2(acc_hi[m][j][0] + acc_lo[m][j][0],
                                    acc_hi[m][j][1] + acc_lo[m][j][1]);
            float2 v1 = make_float2(acc_hi[m][j][2] + acc_lo[m][j][2],
                                    acc_hi[m][j][3] + acc_lo[m][j][3]);
            *(float2*)(C + (size_t)row * 256 + col)       = v0;
            *(float2*)(C + (size_t)(row + 8) * 256 + col) = v1;
        }
    }
}

// ---------------- prep kernels ----------------
__global__ void zero_f(float* p, int n) {
    int i = blockIdx.x * 256 + threadIdx.x;
    if (i < n) p[i] = 0.f;
}

__global__ void nan_split2h(const float* __restrict__ x,
                            __half* __restrict__ p0, __half* __restrict__ p1, int n) {
    int i = blockIdx.x * 256 + threadIdx.x;
    if (i >= n) return;
    float v = x[i]; v = isnan(v) ? 0.f : v;
    H2S s = h2_split(v);
    p0[i] = s.x; p1[i] = s.y;
}

__global__ void build_adj(const int* __restrict__ src, const int* __restrict__ dst,
                          int E, float* __restrict__ A) {
    int e = blockIdx.x * 256 + threadIdx.x;
    if (e >= E) return;
    int s = src[e], d = dst[e];
    int g = d >> 6;
    atomicAdd(&A[((size_t)g << 12) + ((size_t)(d & 63) << 6) + (s & 63)], 1.0f);
}

__global__ void norm_adj(float* __restrict__ A) {
    int row  = blockIdx.x * 8 + (threadIdx.x >> 5);
    int lane = threadIdx.x & 31;
    float* rp = A + (size_t)row * 64;
    float v0 = rp[lane], v1 = rp[lane + 32];
    float s = v0 + v1;
    #pragma unroll
    for (int o = 16; o > 0; o >>= 1) s += __shfl_xor_sync(0xffffffffu, s, o);
    float inv = 1.f / fmaxf(s, 1.f);
    rp[lane] = v0 * inv; rp[lane + 32] = v1 * inv;
}

__global__ void wsplit2h(const float* __restrict__ w,
                         __half* __restrict__ p0, __half* __restrict__ p1, int K) {
    int idx = blockIdx.x * 256 + threadIdx.x;
    if (idx >= K * 256) return;
    int k = idx >> 8, n = idx & 255;
    H2S s = h2_split(w[idx]);
    p0[(size_t)n * K + k] = s.x; p1[(size_t)n * K + k] = s.y;
}

__global__ void cwsplit2(const float* __restrict__ w,
                         __nv_bfloat16* __restrict__ p0, __nv_bfloat16* __restrict__ p1) {
    int idx = blockIdx.x * 256 + threadIdx.x;
    if (idx >= 256 * 1024) return;
    int o = idx >> 10, k = idx & 1023;
    int s = k >> 8, i = k & 255;
    float v = w[((size_t)(o * 256 + i)) * 4 + s];
    __nv_bfloat16 h0 = __float2bfloat16(v);
    p0[idx] = h0;
    p1[idx] = __float2bfloat16(v - __bfloat162float(h0));
}

// lin1 weight planes: p[(ts*256+n)*256+o] = split2(W1[(o*27+ts)*256+n])
__global__ void w1split2(const float* __restrict__ w1,
                         __nv_bfloat16* __restrict__ p0, __nv_bfloat16* __restrict__ p1) {
    int idx = blockIdx.x * 256 + threadIdx.x;
    if (idx >= LOUT * 256 * 256) return;
    int ts = idx >> 16;
    int rem = idx & 65535;
    int n = rem >> 8, o = rem & 255;
    float v = w1[((size_t)(o * LOUT + ts)) * 256 + n];
    __nv_bfloat16 h0 = __float2bfloat16(v);
    p0[idx] = h0;
    p1[idx] = __float2bfloat16(v - __bfloat162float(h0));
}

// ------------- SAGE combine: R1-exact FFMA chains; single-sync, 80KB smem ---
#define CMB_SMZ (16384 + 65536)   // As[64][64] + HLs[64][256]

__global__ __launch_bounds__(256) void sage_combine(
    const float* __restrict__ HL, const float* __restrict__ HR,
    const float* __restrict__ bias, float* __restrict__ Hout,
    __half* __restrict__ p0, __half* __restrict__ p1,
    const float* __restrict__ Aadj, int emit_h, int emit_planes)
{
    extern __shared__ char smraw[];
    float (*As)[64]   = (float(*)[64])smraw;
    float (*HLs)[256] = (float(*)[256])(smraw + 16384);
    int g = blockIdx.x, t = threadIdx.x;
    const float* Ag = Aadj + ((size_t)g << 12);

    #pragma unroll
    for (int h = 0; h < 4; h++) {
        int idx = t + h * 256;
        int n = idx >> 4, k4 = (idx & 15) * 4;
        float4 v = *reinterpret_cast<const float4*>(Ag + (size_t)n * 64 + k4);
        As[k4 + 0][n] = v.x; As[k4 + 1][n] = v.y;
        As[k4 + 2][n] = v.z; As[k4 + 3][n] = v.w;
    }
    #pragma unroll
    for (int h = 0; h < 16; h++) {
        int idx = t + h * 256;               // 0..4095 float4 slots
        int k = idx >> 6, c4 = (idx & 63) * 4;
        *reinterpret_cast<float4*>(&HLs[k][c4]) =
            *reinterpret_cast<const float4*>(HL + ((size_t)(g * 64 + k)) * HH + c4);
    }
    __syncthreads();

    int ngrp = t >> 4;
    int cgrp = t & 15;

    #pragma unroll
    for (int ch = 0; ch < 2; ch++) {
        float acc[4][8];
        #pragma unroll
        for (int i = 0; i < 4; i++)
            #pragma unroll
            for (int j = 0; j < 8; j++) acc[i][j] = 0.f;

        #pragma unroll 4
        for (int k = 0; k < 64; k++) {
            float a[4], b[8];
            *reinterpret_cast<float4*>(&a[0]) = *reinterpret_cast<const float4*>(&As[k][ngrp * 4]);
            *reinterpret_cast<float4*>(&b[0]) =
                *reinterpret_cast<const float4*>(&HLs[k][ch * 128 + cgrp * 8]);
            *reinterpret_cast<float4*>(&b[4]) =
                *reinterpret_cast<const float4*>(&HLs[k][ch * 128 + cgrp * 8 + 4]);
            #pragma unroll
            for (int i = 0; i < 4; i++)
                #pragma unroll
                for (int j = 0; j < 8; j++) acc[i][j] += a[i] * b[j];
        }
        #pragma unroll
        for (int i = 0; i < 4; i++) {
            int n = ngrp * 4 + i;
            size_t base = ((size_t)(g * 64 + n)) * HH + ch * 128 + cgrp * 8;
            #pragma unroll
            for (int j = 0; j < 8; j++) {
                float v = acc[i][j] + bias[ch * 128 + cgrp * 8 + j] + HR[base + j];
                float h = fmaxf(v, 0.f);
                if (emit_h) Hout[base + j] = h;
                if (emit_planes) {
                    H2S s = h2_split(h);
                    p0[base + j] = s.x; p1[base + j] = s.y;
                }
            }
        }
    }
}

// ------------- SortPool (verbatim) -------------------------------------------
__global__ __launch_bounds__(256) void sort_topk2(
    const float* __restrict__ H,
    __nv_bfloat16* __restrict__ t0, __nv_bfloat16* __restrict__ t1)
{
    int g = blockIdx.x, t = threadIdx.x;
    __shared__ float keys[64];
    __shared__ int   sel[KSORT];
    if (t < 64) keys[t] = H[((size_t)(g * 64 + t)) * HH + 255];
    __syncthreads();
    if (t < 64) {
        float kv = keys[t];
        int r = 0;
        #pragma unroll
        for (int m = 0; m < 64; m++) {
            float km = keys[m];
            r += (km > kv) || (km == kv && m < t);
        }
        if (r < KSORT) sel[r] = t;
    }
    __syncthreads();
    for (int idx = t; idx < KSORT * HH; idx += 256) {
        int r = idx >> 8, c = idx & 255;
        float v = H[((size_t)(g * 64 + sel[r])) * HH + c];
        __nv_bfloat16 h0 = __float2bfloat16(v);
        size_t d = (size_t)g * KSORT * HH + idx;
        t0[d] = h0;
        t1[d] = __float2bfloat16(v - __bfloat162float(h0));
    }
}

// ============ conv1d TC GEMM (verbatim R12) ==================================
#define CPROW_B   80
#define CPLANE_B  (128*CPROW_B)
#define CSTAGE_B  (4*CPLANE_B)
#define CSMZ      (2*CSTAGE_B)

__global__ __launch_bounds__(256) void conv_tc(
    const __nv_bfloat16* __restrict__ T0, const __nv_bfloat16* __restrict__ T1,
    const __nv_bfloat16* __restrict__ W0, const __nv_bfloat16* __restrict__ W1,
    __nv_bfloat16* __restrict__ Y0, __nv_bfloat16* __restrict__ Y1,
    const float* __restrict__ bias)
{
    extern __shared__ char smem[];
    const int t    = threadIdx.x;
    const int lane = t & 31;
    const int wid  = t >> 5;
    const int wm   = wid & 3;
    const int wn   = wid >> 2;
    const int m0   = blockIdx.y * 128;
    const int n0   = blockIdx.x * 128;
    const int lr   = lane >> 2;
    const int lc   = lane & 3;
    const int nch  = 32;

    uint32_t sbase = smem_u32(smem);

    auto ld_stage = [&](int stage, int c) {
        uint32_t sb = sbase + stage * CSTAGE_B;
        int kt = c << 5;
        int sp = kt >> 8, ko = kt & 255;
        #pragma unroll
        for (int i = 0; i < 8; i++) {
            int idx = t + i * 256;
            int pl  = idx >> 9;
            int rem = idx & 511;
            int row = rem >> 2, q = rem & 3;
            uint32_t dst = sb + pl * CPLANE_B + row * CPROW_B + q * 16;
            const __nv_bfloat16* src;
            if (pl < 2) {
                const __nv_bfloat16* P = (pl == 0) ? T0 : T1;
                int m = m0 + row;
                int g = m / 27, tp = m - g * 27;
                src = P + (size_t)((g * 30 + tp + sp) * 256 + ko) + q * 8;
            } else {
                const __nv_bfloat16* P = (pl == 2) ? W0 : W1;
                src = P + (size_t)(n0 + row) * 1024 + kt + q * 8;
            }
            cpasync16(dst, src);
        }
        asm volatile("cp.async.commit_group;" ::: "memory");
    };

    float acc[2][8][4];
    #pragma unroll
    for (int m = 0; m < 2; m++)
        #pragma unroll
        for (int j = 0; j < 8; j++)
            #pragma unroll
            for (int q = 0; q < 4; q++) acc[m][j][q] = 0.f;

    ld_stage(0, 0);
    ld_stage(1, 1);

    for (int c = 0; c < nch; c++) {
        if (c + 1 < nch) asm volatile("cp.async.wait_group 1;" ::: "memory");
        else             asm volatile("cp.async.wait_group 0;" ::: "memory");
        __syncthreads();

        const char* sb = smem + (c & 1) * CSTAGE_B;

        #pragma unroll
        for (int s = 0; s < 2; s++) {
            int kc = s * 32 + lc * 4;
            uint32_t A0f[2][4], A1f[2][4];
            #pragma unroll
            for (int m = 0; m < 2; m++) {
                int r0 = (wm * 32 + m * 16 + lr) * CPROW_B;
                int r1 = r0 + 8 * CPROW_B;
                A0f[m][0] = *(const uint32_t*)(sb + r0 + kc);
                A0f[m][1] = *(const uint32_t*)(sb + r1 + kc);
                A0f[m][2] = *(const uint32_t*)(sb + r0 + kc + 16);
                A0f[m][3] = *(const uint32_t*)(sb + r1 + kc + 16);
                A1f[m][0] = *(const uint32_t*)(sb + CPLANE_B + r0 + kc);
                A1f[m][1] = *(const uint32_t*)(sb + CPLANE_B + r1 + kc);
                A1f[m][2] = *(const uint32_t*)(sb + CPLANE_B + r0 + kc + 16);
                A1f[m][3] = *(const uint32_t*)(sb + CPLANE_B + r1 + kc + 16);
            }
            #pragma unroll
            for (int j = 0; j < 8; j++) {
                int nr = (wn * 64 + j * 8 + lr) * CPROW_B;
                uint32_t b00 = *(const uint32_t*)(sb + 2*CPLANE_B + nr + kc);
                uint32_t b01 = *(const uint32_t*)(sb + 2*CPLANE_B + nr + kc + 16);
                uint32_t b10 = *(const uint32_t*)(sb + 3*CPLANE_B + nr + kc);
                uint32_t b11 = *(const uint32_t*)(sb + 3*CPLANE_B + nr + kc + 16);
                #pragma unroll
                for (int m = 0; m < 2; m++)
                    mma16bf(acc[m][j], A0f[m][0], A0f[m][1], A0f[m][2], A0f[m][3], b00, b01);
                #pragma unroll
                for (int m = 0; m < 2; m++)
                    mma16bf(acc[m][j], A0f[m][0], A0f[m][1], A0f[m][2], A0f[m][3], b10, b11);
                #pragma unroll
                for (int m = 0; m < 2; m++)
                    mma16bf(acc[m][j], A1f[m][0], A1f[m][1], A1f[m][2], A1f[m][3], b00, b01);
            }
        }
        if (c + 2 < nch) {
            __syncthreads();
            ld_stage(c & 1, c + 2);
        }
    }

    #pragma unroll
    for (int m = 0; m < 2; m++) {
        int row = m0 + wm * 32 + m * 16 + lr;
        #pragma unroll
        for (int j = 0; j < 8; j++) {
            int col = n0 + wn * 64 + j * 8 + 2 * lc;
            float b0 = bias[col], b1 = bias[col + 1];
            float y00 = fmaxf(acc[m][j][0] + b0, 0.f);
            float y01 = fmaxf(acc[m][j][1] + b1, 0.f);
            float y10 = fmaxf(acc[m][j][2] + b0, 0.f);
            float y11 = fmaxf(acc[m][j][3] + b1, 0.f);
            __nv_bfloat162 s00 = bf2_split(y00), s01 = bf2_split(y01);
            __nv_bfloat162 s10 = bf2_split(y10), s11 = bf2_split(y11);
            size_t o0 = (size_t)row * 256 + col;
            size_t o1 = (size_t)(row + 8) * 256 + col;
            __nv_bfloat162 p;
            p.x = s00.x; p.y = s01.x; *(__nv_bfloat162*)(Y0 + o0) = p;
            p.x = s00.y; p.y = s01.y; *(__nv_bfloat162*)(Y1 + o0) = p;
            p.x = s10.x; p.y = s11.x; *(__nv_bfloat162*)(Y0 + o1) = p;
            p.x = s10.y; p.y = s11.y; *(__nv_bfloat162*)(Y1 + o1) = p;
        }
    }
}

// ============ lin1 TC GEMM (verbatim R12) ====================================
__global__ __launch_bounds__(256) void lin1_tc(
    const __nv_bfloat16* __restrict__ Y0, const __nv_bfloat16* __restrict__ Y1,
    const __nv_bfloat16* __restrict__ P0, const __nv_bfloat16* __restrict__ P1,
    float* __restrict__ Z)
{
    extern __shared__ char smem[];
    const int t    = threadIdx.x;
    const int lane = t & 31;
    const int wid  = t >> 5;
    const int wm   = wid & 3;
    const int wn   = wid >> 2;
    const int m0   = blockIdx.y * 128;
    const int n0   = blockIdx.x * 128;
    const int ts   = blockIdx.z;
    const int lr   = lane >> 2;
    const int lc   = lane & 3;
    const int nch  = 8;

    uint32_t sbase = smem_u32(smem);

    auto ld_stage = [&](int stage, int c) {
        uint32_t sb = sbase + stage * CSTAGE_B;
        int kt = c << 5;
        #pragma unroll
        for (int i = 0; i < 8; i++) {
            int idx = t + i * 256;
            int pl  = idx >> 9;
            int rem = idx & 511;
            int row = rem >> 2, q = rem & 3;
            uint32_t dst = sb + pl * CPLANE_B + row * CPROW_B + q * 16;
            const __nv_bfloat16* src;
            if (pl < 2) {
                const __nv_bfloat16* P = (pl == 0) ? Y0 : Y1;
                src = P + ((size_t)((m0 + row) * LOUT + ts)) * 256 + kt + q * 8;
            } else {
                const __nv_bfloat16* P = (pl == 2) ? P0 : P1;
                src = P + ((size_t)(ts * 256 + n0 + row)) * 256 + kt + q * 8;
            }
            cpasync16(dst, src);
        }
        asm volatile("cp.async.commit_group;" ::: "memory");
    };

    float acc[2][8][4];
    #pragma unroll
    for (int m = 0; m < 2; m++)
        #pragma unroll
        for (int j = 0; j < 8; j++)
            #pragma unroll
            for (int q = 0; q < 4; q++) acc[m][j][q] = 0.f;

    ld_stage(0, 0);
    ld_stage(1, 1);

    for (int c = 0; c < nch; c++) {
        if (c + 1 < nch) asm volatile("cp.async.wait_group 1;" ::: "memory");
        else             asm volatile("cp.async.wait_group 0;" ::: "memory");
        __syncthreads();

        const char* sb = smem + (c & 1) * CSTAGE_B;

        #pragma unroll
        for (int s = 0; s < 2; s++) {
            int kc = s * 32 + lc * 4;
            uint32_t A0f[2][4], A1f[2][4];
            #pragma unroll
            for (int m = 0; m < 2; m++) {
                int r0 = (wm * 32 + m * 16 + lr) * CPROW_B;
                int r1 = r0 + 8 * CPROW_B;
                A0f[m][0] = *(const uint32_t*)(sb + r0 + kc);
                A0f[m][1] = *(const uint32_t*)(sb + r1 + kc);
                A0f[m][2] = *(const uint32_t*)(sb + r0 + kc + 16);
                A0f[m][3] = *(const uint32_t*)(sb + r1 + kc + 16);
                A1f[m][0] = *(const uint32_t*)(sb + CPLANE_B + r0 + kc);
                A1f[m][1] = *(const uint32_t*)(sb + CPLANE_B + r1 + kc);
                A1f[m][2] = *(const uint32_t*)(sb + CPLANE_B + r0 + kc + 16);
                A1f[m][3] = *(const uint32_t*)(sb + CPLANE_B + r1 + kc + 16);
            }
            #pragma unroll
            for (int j = 0; j < 8; j++) {
                int nr = (wn * 64 + j * 8 + lr) * CPROW_B;
                uint32_t b00 = *(const uint32_t*)(sb + 2*CPLANE_B + nr + kc);
                uint32_t b01 = *(const uint32_t*)(sb + 2*CPLANE_B + nr + kc + 16);
                uint32_t b10 = *(const uint32_t*)(sb + 3*CPLANE_B + nr + kc);
                uint32_t b11 = *(const uint32_t*)(sb + 3*CPLANE_B + nr + kc + 16);
                #pragma unroll
                for (int m = 0; m < 2; m++)
                    mma16bf(acc[m][j], A0f[m][0], A0f[m][1], A0f[m][2], A0f[m][3], b00, b01);
                #pragma unroll
                for (int m = 0; m < 2; m++)
                    mma16bf(acc[m][j], A0f[m][0], A0f[m][1], A0f[m][2], A0f[m][3], b10, b11);
                #pragma unroll
                for (int m = 0; m < 2; m++)
                    mma16bf(acc[m][j], A1f[m][0], A1f[m][1], A1f[m][2], A1f[m][3], b00, b01);
            }
        }
        if (c + 2 < nch) {
            __syncthreads();
            ld_stage(c & 1, c + 2);
        }
    }

    #pragma unroll
    for (int m = 0; m < 2; m++) {
        int g = m0 + wm * 32 + m * 16 + lr;
        #pragma unroll
        for (int j = 0; j < 8; j++) {
            int col = n0 + wn * 64 + j * 8 + 2 * lc;
            atomicAdd(&Z[(size_t)g * 256 + col],           acc[m][j][0]);
            atomicAdd(&Z[(size_t)g * 256 + col + 1],       acc[m][j][1]);
            atomicAdd(&Z[(size_t)(g + 8) * 256 + col],     acc[m][j][2]);
            atomicAdd(&Z[(size_t)(g + 8) * 256 + col + 1], acc[m][j][3]);
        }
    }
}

// ------------- final MLP (verbatim) ------------------------------------------
__global__ __launch_bounds__(256) void mlp_kernel(
    const float* __restrict__ z1acc, const float* __restrict__ b1,
    const float* __restrict__ W2,   const float* __restrict__ b2,
    const float* __restrict__ W3,   const float* __restrict__ b3,
    float* __restrict__ out)
{
    int g = blockIdx.x, t = threadIdx.x;
    __shared__ float s1[256];
    __shared__ float s2[128];
    s1[t] = fmaxf(z1acc[(size_t)g * 256 + t] + b1[t], 0.f);
    __syncthreads();
    if (t < 128) {
        float acc = b2[t];
        #pragma unroll 8
        for (int k = 0; k < 256; k++) acc += s1[k] * W2[(size_t)k * 128 + t];
        s2[t] = fmaxf(acc, 0.f);
    }
    __syncthreads();
    if (t < 10) {
        float acc = b3[t];
        #pragma unroll
        for (int k = 0; k < 128; k++) acc += s2[k] * W3[(size_t)k * 10 + t];
        out[(size_t)g * 10 + t] = fmaxf(acc, 0.f);
    }
}

// ---------------- launch ----------------
extern "C" void kernel_launch(void* const* d_in, const int* in_sizes, int n_in,
                              void* d_out, int out_size)
{
    const float* x  = (const float*)d_in[0];
    const int*   ei = (const int*)  d_in[1];
    int E = in_sizes[1] / 2;
    const int* src = ei;
    const int* dst = ei + E;

    const float* wl[4] = {(const float*)d_in[3], (const float*)d_in[6],
                          (const float*)d_in[9], (const float*)d_in[12]};
    const float* wr[4] = {(const float*)d_in[4], (const float*)d_in[7],
                          (const float*)d_in[10], (const float*)d_in[13]};
    const float* sb[4] = {(const float*)d_in[5], (const float*)d_in[8],
                          (const float*)d_in[11], (const float*)d_in[14]};
    const float* convw = (const float*)d_in[15];
    const float* convb = (const float*)d_in[16];
    const float* l1w   = (const float*)d_in[17];
    const float* l1b   = (const float*)d_in[18];
    const float* l2w   = (const float*)d_in[19];
    const float* l2b   = (const float*)d_in[20];
    const float* ow    = (const float*)d_in[21];
    const float* ob    = (const float*)d_in[22];

    float *pA, *pH, *pHL, *pHR, *pZ1;
    __half *pa0, *pa1, *pb0, *pb1, *pw0, *pw1;
    __nv_bfloat16 *pt0, *pt1, *pc0, *pc1, *py0, *py1, *pl0, *pl1;
    cudaGetSymbolAddress((void**)&pA,  g_A);
    cudaGetSymbolAddress((void**)&pH,  g_H);
    cudaGetSymbolAddress((void**)&pHL, g_HL);
    cudaGetSymbolAddress((void**)&pHR, g_HR);
    cudaGetSymbolAddress((void**)&pZ1, g_z1);
    cudaGetSymbolAddress((void**)&pa0, g_a0);
    cudaGetSymbolAddress((void**)&pa1, g_a1);
    cudaGetSymbolAddress((void**)&pb0, g_b0);
    cudaGetSymbolAddress((void**)&pb1, g_b1);
    cudaGetSymbolAddress((void**)&pw0, g_w0);
    cudaGetSymbolAddress((void**)&pw1, g_w1);
    cudaGetSymbolAddress((void**)&pt0, g_t0);
    cudaGetSymbolAddress((void**)&pt1, g_t1);
    cudaGetSymbolAddress((void**)&pc0, g_c0);
    cudaGetSymbolAddress((void**)&pc1, g_c1);
    cudaGetSymbolAddress((void**)&py0, g_y0);
    cudaGetSymbolAddress((void**)&py1, g_y1);
    cudaGetSymbolAddress((void**)&pl0, g_l0);
    cudaGetSymbolAddress((void**)&pl1, g_l1);

    cudaFuncSetAttribute(gemm_sage_tc, cudaFuncAttributeMaxDynamicSharedMemorySize, GSMZ);
    cudaFuncSetAttribute(conv_tc, cudaFuncAttributeMaxDynamicSharedMemorySize, CSMZ);
    cudaFuncSetAttribute(lin1_tc, cudaFuncAttributeMaxDynamicSharedMemorySize, CSMZ);
    cudaFuncSetAttribute(sage_combine, cudaFuncAttributeMaxDynamicSharedMemorySize, CMB_SMZ);

    // preprocessing
    zero_f<<<(NB*PP*PP + 255)/256, 256>>>(pA, NB*PP*PP);
    build_adj<<<(E + 255)/256, 256>>>(src, dst, E, pA);
    norm_adj<<<NN/8, 256>>>(pA);
    nan_split2h<<<(NN*FF + 255)/256, 256>>>(x, pa0, pa1, NN*FF);
    zero_f<<<(NB*HH + 255)/256, 256>>>(pZ1, NB*HH);
    for (int l = 0; l < 4; l++) {
        int K = (l == 0) ? FF : HH;
        size_t o0 = (size_t)(2*l)   * HH * HH;
        size_t o1 = (size_t)(2*l+1) * HH * HH;
        wsplit2h<<<(K*256 + 255)/256, 256>>>(wl[l], pw0+o0, pw1+o0, K);
        wsplit2h<<<(K*256 + 255)/256, 256>>>(wr[l], pw0+o1, pw1+o1, K);
    }
    cwsplit2<<<(256*1024 + 255)/256, 256>>>(convw, pc0, pc1);
    w1split2<<<(LOUT*256*256 + 255)/256, 256>>>(l1w, pl0, pl1);

    // 4 SAGE layers — fp16 2-plane 3-product TC GEMMs + exact combine
    __half *i0 = pa0, *i1 = pa1;
    __half *o0 = pb0, *o1 = pb1;
    for (int l = 0; l < 4; l++) {
        int K = (l == 0) ? FF : HH;
        size_t f0 = (size_t)(2*l)   * HH * HH;
        size_t f1 = (size_t)(2*l+1) * HH * HH;
        gemm_sage_tc<<<dim3(8, NN/128), 256, GSMZ>>>(
            i0, i1,
            pw0+f0, pw1+f0,
            pw0+f1, pw1+f1,
            pHL, pHR, K);
        int last = (l == 3);
        sage_combine<<<NB, 256, CMB_SMZ>>>(pHL, pHR, sb[l], pH, o0, o1, pA,
                                           last, !last);
        __half* tmp;
        tmp = i0; i0 = o0; o0 = tmp;
        tmp = i1; i1 = o1; o1 = tmp;
    }

    // SortPool (exact fp32 keys) -> conv1d TC -> lin1 TC -> MLP
    sort_topk2<<<NB, 256>>>(pH, pt0, pt1);
    conv_tc<<<dim3(2, MCONV/128), 256, CSMZ>>>(pt0, pt1, pc0, pc1, py0, py1, convb);
    lin1_tc<<<dim3(2, 4, LOUT), 256, CSMZ>>>(py0, py1, pl0, pl1, pZ1);
    mlp_kernel<<<NB, 256>>>(pZ1, l1b, l2w, l2b, ow, ob, (float*)d_out);
}

// round 14
// speedup vs baseline: 1.0463x; 1.0463x over previous
#include <cuda_runtime.h>
#include <cuda_bf16.h>
#include <cuda_fp16.h>
#include <math.h>
#include <stdint.h>

// ---------------- problem constants ----------------
#define NB       512
#define PP       64
#define NN       (NB*PP)      // 32768
#define FF       128
#define HH       256
#define KSORT    30
#define LOUT     27
#define MCONV    (NB*LOUT)    // 13824

// ---------------- static scratch ----------------
__device__ __align__(16) float g_A  [NB*PP*PP];
__device__ __align__(16) float g_H  [NN*HH];      // fp32 activations (sort keys)
__device__ __align__(16) float g_HL [NN*HH];
__device__ __align__(16) float g_HR [NN*HH];
__device__ __align__(16) float g_z1 [NB*HH];
// fp16 2-plane activations ping/pong
__device__ __align__(16) __half g_a0[NN*HH], g_a1[NN*HH];
__device__ __align__(16) __half g_b0[NN*HH], g_b1[NN*HH];
// fp16 sage weight planes [8 mats][256][K]
__device__ __align__(16) __half g_w0[8*HH*HH], g_w1[8*HH*HH];
// conv path (bf16 2-plane)
__device__ __align__(16) __nv_bfloat16 g_t0[NB*KSORT*HH], g_t1[NB*KSORT*HH];
__device__ __align__(16) __nv_bfloat16 g_c0[HH*1024],     g_c1[HH*1024];
// conv output as bf16 split-2 planes [(g,tp)][o]
__device__ __align__(16) __nv_bfloat16 g_y0[MCONV*HH], g_y1[MCONV*HH];
// lin1 weight planes [ts][n][o]
__device__ __align__(16) __nv_bfloat16 g_l0[LOUT*HH*HH], g_l1[LOUT*HH*HH];

// ---------------- helpers ----------------
__device__ __forceinline__ uint32_t smem_u32(const void* p) {
    uint32_t a;
    asm("{ .reg .u64 t; cvta.to.shared.u64 t, %1; cvt.u32.u64 %0, t; }" : "=r"(a) : "l"(p));
    return a;
}
__device__ __forceinline__ void cpasync16(uint32_t dst, const void* src) {
    asm volatile("cp.async.cg.shared.global [%0], [%1], 16;" :: "r"(dst), "l"(src));
}
__device__ __forceinline__ void ldsm4(uint32_t* r, uint32_t addr) {
    asm volatile("ldmatrix.sync.aligned.m8n8.x4.shared.b16 {%0,%1,%2,%3}, [%4];"
        : "=r"(r[0]), "=r"(r[1]), "=r"(r[2]), "=r"(r[3]) : "r"(addr));
}
__device__ __forceinline__ void mma16bf(float* d, uint32_t a0, uint32_t a1,
                                        uint32_t a2, uint32_t a3,
                                        uint32_t b0, uint32_t b1) {
    asm volatile(
        "mma.sync.aligned.m16n8k16.row.col.f32.bf16.bf16.f32 "
        "{%0,%1,%2,%3}, {%4,%5,%6,%7}, {%8,%9}, {%0,%1,%2,%3};"
        : "+f"(d[0]), "+f"(d[1]), "+f"(d[2]), "+f"(d[3])
        : "r"(a0), "r"(a1), "r"(a2), "r"(a3), "r"(b0), "r"(b1));
}
__device__ __forceinline__ void mma16h(float* d, const uint32_t* a,
                                       uint32_t b0, uint32_t b1) {
    asm volatile(
        "mma.sync.aligned.m16n8k16.row.col.f32.f16.f16.f32 "
        "{%0,%1,%2,%3}, {%4,%5,%6,%7}, {%8,%9}, {%0,%1,%2,%3};"
        : "+f"(d[0]), "+f"(d[1]), "+f"(d[2]), "+f"(d[3])
        : "r"(a[0]), "r"(a[1]), "r"(a[2]), "r"(a[3]), "r"(b0), "r"(b1));
}
struct H2S { __half x, y; };
__device__ __forceinline__ H2S h2_split(float v) {
    H2S r;
    r.x = __float2half_rn(v);
    float rem = v - __half2float(r.x);
    r.y = __float2half_rn(rem);
    return r;
}
__device__ __forceinline__ __nv_bfloat162 bf2_split(float v) {
    __nv_bfloat16 h0 = __float2bfloat16(v);
    __nv_bfloat16 h1 = __float2bfloat16(v - __bfloat162float(h0));
    __nv_bfloat162 r; r.x = h0; r.y = h1; return r;
}

// ===== SAGE GEMM (verbatim R12/R11 schedule: key path, bit-identical) =======
#define GPROW_B   80
#define GA_PLANE  (128*GPROW_B)
#define GB_PLANE  (64*GPROW_B)
#define GSTAGE    (2*GA_PLANE + 2*GB_PLANE)
#define GSMZ      (3*GSTAGE)

__global__ __launch_bounds__(256, 2) void gemm_sage_tc(
    const __half* __restrict__ A0, const __half* __restrict__ A1,
    const __half* __restrict__ L0, const __half* __restrict__ L1,
    const __half* __restrict__ R0, const __half* __restrict__ R1,
    float* __restrict__ Cl, float* __restrict__ Cr, int K)
{
    extern __shared__ char smem[];
    const int t    = threadIdx.x;
    const int lane = t & 31;
    const int wid  = t >> 5;
    const int wm   = wid & 3;
    const int wn   = wid >> 2;
    const int m0   = blockIdx.y * 128;
    const int sel  = blockIdx.x >> 2;
    const int n0   = (blockIdx.x & 3) * 64;
    const int lr   = lane >> 2;
    const int lc   = lane & 3;
    const int nch  = K >> 5;

    const __half* W0 = sel ? R0 : L0;
    const __half* W1 = sel ? R1 : L1;
    float* C = sel ? Cr : Cl;

    uint32_t sbase = smem_u32(smem);

    const int l15    = lane & 15;
    const int koff_a = (lane >> 4) * 16;
    const int brow_l = ((lane >> 4) << 3) + (lane & 7);
    const int koff_b = ((lane >> 3) & 1) * 16;

    auto ld_stage = [&](int stage, int c) {
        uint32_t sb = sbase + stage * GSTAGE;
        int kt = c << 5;
        #pragma unroll
        for (int i = 0; i < 6; i++) {
            int idx = t + i * 256;
            if (idx < 1024) {
                int pl = idx >> 9, rem = idx & 511;
                int row = rem >> 2, q = rem & 3;
                const __half* P = pl ? A1 : A0;
                cpasync16(sb + pl * GA_PLANE + row * GPROW_B + q * 16,
                          P + (size_t)(m0 + row) * K + kt + q * 8);
            } else {
                int idx2 = idx - 1024;
                int pl = idx2 >> 8, rem = idx2 & 255;
                int row = rem >> 2, q = rem & 3;
                const __half* P = pl ? W1 : W0;
                cpasync16(sb + 2 * GA_PLANE + pl * GB_PLANE + row * GPROW_B + q * 16,
                          P + (size_t)(n0 + row) * K + kt + q * 8);
            }
        }
        asm volatile("cp.async.commit_group;" ::: "memory");
    };

    float acc_hi[2][4][4], acc_lo[2][4][4];
    #pragma unroll
    for (int m = 0; m < 2; m++)
        #pragma unroll
        for (int j = 0; j < 4; j++)
            #pragma unroll
            for (int q = 0; q < 4; q++) { acc_hi[m][j][q] = 0.f; acc_lo[m][j][q] = 0.f; }

    ld_stage(0, 0);
    if (nch > 1) ld_stage(1, 1);

    int st = 0;
    for (int c = 0; c < nch; c++) {
        if (c + 1 < nch) asm volatile("cp.async.wait_group 1;" ::: "memory");
        else             asm volatile("cp.async.wait_group 0;" ::: "memory");
        __syncthreads();
        if (c + 2 < nch) {
            int st2 = st + 2; if (st2 >= 3) st2 -= 3;
            ld_stage(st2, c + 2);
        }

        uint32_t sb = sbase + st * GSTAGE;

        #pragma unroll
        for (int s = 0; s < 2; s++) {
            uint32_t a0f[2][4], a1f[2][4];
            #pragma unroll
            for (int m = 0; m < 2; m++) {
                uint32_t rowb = (uint32_t)((wm * 32 + m * 16 + l15) * GPROW_B
                                           + s * 32 + koff_a);
                ldsm4(a0f[m], sb + rowb);
                ldsm4(a1f[m], sb + GA_PLANE + rowb);
            }
            #pragma unroll
            for (int jp = 0; jp < 2; jp++) {
                uint32_t nrow = sb + 2 * GA_PLANE
                    + (uint32_t)((wn * 32 + jp * 16 + brow_l) * GPROW_B
                                 + s * 32 + koff_b);
                uint32_t b0[4], b1[4];
                ldsm4(b0, nrow);
                ldsm4(b1, nrow + GB_PLANE);
                // pass 1: all hi (a0*b0)
                #pragma unroll
                for (int jj = 0; jj < 2; jj++)
                    #pragma unroll
                    for (int m = 0; m < 2; m++)
                        mma16h(acc_hi[m][jp*2+jj], a0f[m], b0[2*jj], b0[2*jj+1]);
                // pass 2: all lo (a0*b1)
                #pragma unroll
                for (int jj = 0; jj < 2; jj++)
                    #pragma unroll
                    for (int m = 0; m < 2; m++)
                        mma16h(acc_lo[m][jp*2+jj], a0f[m], b1[2*jj], b1[2*jj+1]);
                // pass 3: all lo (a1*b0)
                #pragma unroll
                for (int jj = 0; jj < 2; jj++)
                    #pragma unroll
                    for (int m = 0; m < 2; m++)
                        mma16h(acc_lo[m][jp*2+jj], a1f[m], b0[2*jj], b0[2*jj+1]);
            }
        }
        if (++st == 3) st = 0;
    }

    #pragma unroll
    for (int m = 0; m < 2; m++) {
        int row = m0 + wm * 32 + m * 16 + lr;
        #pragma unroll
        for (int j = 0; j < 4; j++) {
            int col = n0 + wn * 32 + j * 8 + 2 * lc;
            float2 v0 = make_float2(acc_hi[m][j][0] + acc_lo[m][j][0],
                                    acc_hi[m][j][1] + acc_lo[m][j][1]);
            float2 v1 = make_float2(acc_hi[m][j][2] + acc_lo[m][j][2],
                                    acc_hi[m][j][3] + acc_lo[m][j][3]);
            *(float2*)(C + (size_t)row * 256 + col)       = v0;
            *(float2*)(C + (size_t)(row + 8) * 256 + col) = v1;
        }
    }
}

// ---------------- prep kernels ----------------
__global__ void zero_f(float* p, int n) {
    int i = blockIdx.x * 256 + threadIdx.x;
    if (i < n) p[i] = 0.f;
}

__global__ void nan_split2h(const float* __restrict__ x,
                            __half* __restrict__ p0, __half* __restrict__ p1, int n) {
    int i = blockIdx.x * 256 + threadIdx.x;
    if (i >= n) return;
    float v = x[i]; v = isnan(v) ? 0.f : v;
    H2S s = h2_split(v);
    p0[i] = s.x; p1[i] = s.y;
}

__global__ void build_adj(const int* __restrict__ src, const int* __restrict__ dst,
                          int E, float* __restrict__ A) {
    int e = blockIdx.x * 256 + threadIdx.x;
    if (e >= E) return;
    int s = src[e], d = dst[e];
    int g = d >> 6;
    atomicAdd(&A[((size_t)g << 12) + ((size_t)(d & 63) << 6) + (s & 63)], 1.0f);
}

__global__ void norm_adj(float* __restrict__ A) {
    int row  = blockIdx.x * 8 + (threadIdx.x >> 5);
    int lane = threadIdx.x & 31;
    float* rp = A + (size_t)row * 64;
    float v0 = rp[lane], v1 = rp[lane + 32];
    float s = v0 + v1;
    #pragma unroll
    for (int o = 16; o > 0; o >>= 1) s += __shfl_xor_sync(0xffffffffu, s, o);
    float inv = 1.f / fmaxf(s, 1.f);
    rp[lane] = v0 * inv; rp[lane + 32] = v1 * inv;
}

// ===== merged weight-split prep: all sage/conv/lin1 planes in ONE launch ====
// Element-wise identical to the former wsplit2h/cwsplit2/w1split2 kernels.
#define W1_ELEMS   (LOUT*256*256)            // 1769472
#define CV_ELEMS   (256*1024)                // 262144
#define SG_ELEMS   (2*(128+256+256+256)*256) // 458752
#define PREP_TOTAL (W1_ELEMS + CV_ELEMS + SG_ELEMS)

__global__ void prep_split(
    const float* __restrict__ wl0, const float* __restrict__ wr0,
    const float* __restrict__ wl1, const float* __restrict__ wr1,
    const float* __restrict__ wl2, const float* __restrict__ wr2,
    const float* __restrict__ wl3, const float* __restrict__ wr3,
    const float* __restrict__ convw, const float* __restrict__ l1w,
    __half* __restrict__ pw0, __half* __restrict__ pw1,
    __nv_bfloat16* __restrict__ pc0, __nv_bfloat16* __restrict__ pc1,
    __nv_bfloat16* __restrict__ pl0, __nv_bfloat16* __restrict__ pl1)
{
    int idx = blockIdx.x * 256 + threadIdx.x;
    if (idx >= PREP_TOTAL) return;
    if (idx < W1_ELEMS) {
        // lin1 planes: p[(ts*256+n)*256+o] = split2(W1[(o*27+ts)*256+n])
        int ts = idx >> 16;
        int rem = idx & 65535;
        int n = rem >> 8, o = rem & 255;
        float v = l1w[((size_t)(o * LOUT + ts)) * 256 + n];
        __nv_bfloat16 h0 = __float2bfloat16(v);
        pl0[idx] = h0;
        pl1[idx] = __float2bfloat16(v - __bfloat162float(h0));
    } else if (idx < W1_ELEMS + CV_ELEMS) {
        // conv planes: p[o][s*256+i] = split2(w[(o*256+i)*4+s])
        int i2 = idx - W1_ELEMS;
        int o = i2 >> 10, k = i2 & 1023;
        int s = k >> 8, i = k & 255;
        float v = convw[((size_t)(o * 256 + i)) * 4 + s];
        __nv_bfloat16 h0 = __float2bfloat16(v);
        pc0[i2] = h0;
        pc1[i2] = __float2bfloat16(v - __bfloat162float(h0));
    } else {
        // sage planes: transpose+split [K][256] -> [256][K] fp16 pair
        int i2 = idx - (W1_ELEMS + CV_ELEMS);
        int mat, off, K;
        if (i2 < 65536) { mat = i2 >> 15; off = i2 & 32767; K = 128; }
        else {
            int j = i2 - 65536;
            mat = 2 + (j >> 16); off = j & 65535; K = 256;
        }
        const float* src;
        switch (mat) {
            case 0: src = wl0; break;
            case 1: src = wr0; break;
            case 2: src = wl1; break;
            case 3: src = wr1; break;
            case 4: src = wl2; break;
            case 5: src = wr2; break;
            case 6: src = wl3; break;
            default: src = wr3; break;
        }
        int k = off >> 8, n = off & 255;
        H2S s = h2_split(src[off]);
        size_t d = (size_t)mat * (HH * HH) + (size_t)n * K + k;
        pw0[d] = s.x; pw1[d] = s.y;
    }
}

// ------------- SAGE combine (verbatim R12: R1-exact chains, 4 syncs) --------
__global__ __launch_bounds__(256) void sage_combine(
    const float* __restrict__ HL, const float* __restrict__ HR,
    const float* __restrict__ bias, float* __restrict__ Hout,
    __half* __restrict__ p0, __half* __restrict__ p1,
    const float* __restrict__ Aadj, int emit_h, int emit_planes)
{
    __shared__ float As[64][64];
    __shared__ float HLs[64][128];
    int g = blockIdx.x, t = threadIdx.x;
    const float* Ag = Aadj + ((size_t)g << 12);

    #pragma unroll
    for (int h = 0; h < 4; h++) {
        int idx = t + h * 256;
        int n = idx >> 4, k4 = (idx & 15) * 4;
        float4 v = *reinterpret_cast<const float4*>(Ag + (size_t)n * 64 + k4);
        As[k4 + 0][n] = v.x; As[k4 + 1][n] = v.y;
        As[k4 + 2][n] = v.z; As[k4 + 3][n] = v.w;
    }

    int ngrp = t >> 4;
    int cgrp = t & 15;

    for (int ch = 0; ch < 2; ch++) {
        __syncthreads();
        #pragma unroll
        for (int h = 0; h < 8; h++) {
            int idx = t + h * 256;
            int k = idx >> 5, c4 = (idx & 31) * 4;
            *reinterpret_cast<float4*>(&HLs[k][c4]) =
                *reinterpret_cast<const float4*>(HL + ((size_t)(g * 64 + k)) * HH + ch * 128 + c4);
        }
        __syncthreads();

        float acc[4][8];
        #pragma unroll
        for (int i = 0; i < 4; i++)
            #pragma unroll
            for (int j = 0; j < 8; j++) acc[i][j] = 0.f;

        #pragma unroll 4
        for (int k = 0; k < 64; k++) {
            float a[4], b[8];
            *reinterpret_cast<float4*>(&a[0]) = *reinterpret_cast<const float4*>(&As[k][ngrp * 4]);
            *reinterpret_cast<float4*>(&b[0]) = *reinterpret_cast<const float4*>(&HLs[k][cgrp * 8]);
            *reinterpret_cast<float4*>(&b[4]) = *reinterpret_cast<const float4*>(&HLs[k][cgrp * 8 + 4]);
            #pragma unroll
            for (int i = 0; i < 4; i++)
                #pragma unroll
                for (int j = 0; j < 8; j++) acc[i][j] += a[i] * b[j];
        }
        #pragma unroll
        for (int i = 0; i < 4; i++) {
            int n = ngrp * 4 + i;
            size_t base = ((size_t)(g * 64 + n)) * HH + ch * 128 + cgrp * 8;
            #pragma unroll
            for (int j = 0; j < 8; j++) {
                float v = acc[i][j] + bias[ch * 128 + cgrp * 8 + j] + HR[base + j];
                float h = fmaxf(v, 0.f);
                if (emit_h) Hout[base + j] = h;
                if (emit_planes) {
                    H2S s = h2_split(h);
                    p0[base + j] = s.x; p1[base + j] = s.y;
                }
            }
        }
    }
}

// ------------- SortPool (verbatim) -------------------------------------------
__global__ __launch_bounds__(256) void sort_topk2(
    const float* __restrict__ H,
    __nv_bfloat16* __restrict__ t0, __nv_bfloat16* __restrict__ t1)
{
    int g = blockIdx.x, t = threadIdx.x;
    __shared__ float keys[64];
    __shared__ int   sel[KSORT];
    if (t < 64) keys[t] = H[((size_t)(g * 64 + t)) * HH + 255];
    __syncthreads();
    if (t < 64) {
        float kv = keys[t];
        int r = 0;
        #pragma unroll
        for (int m = 0; m < 64; m++) {
            float km = keys[m];
            r += (km > kv) || (km == kv && m < t);
        }
        if (r < KSORT) sel[r] = t;
    }
    __syncthreads();
    for (int idx = t; idx < KSORT * HH; idx += 256) {
        int r = idx >> 8, c = idx & 255;
        float v = H[((size_t)(g * 64 + sel[r])) * HH + c];
        __nv_bfloat16 h0 = __float2bfloat16(v);
        size_t d = (size_t)g * KSORT * HH + idx;
        t0[d] = h0;
        t1[d] = __float2bfloat16(v - __bfloat162float(h0));
    }
}

// ============ conv1d TC GEMM (verbatim R12) ==================================
#define CPROW_B   80
#define CPLANE_B  (128*CPROW_B)
#define CSTAGE_B  (4*CPLANE_B)
#define CSMZ      (2*CSTAGE_B)

__global__ __launch_bounds__(256) void conv_tc(
    const __nv_bfloat16* __restrict__ T0, const __nv_bfloat16* __restrict__ T1,
    const __nv_bfloat16* __restrict__ W0, const __nv_bfloat16* __restrict__ W1,
    __nv_bfloat16* __restrict__ Y0, __nv_bfloat16* __restrict__ Y1,
    const float* __restrict__ bias)
{
    extern __shared__ char smem[];
    const int t    = threadIdx.x;
    const int lane = t & 31;
    const int wid  = t >> 5;
    const int wm   = wid & 3;
    const int wn   = wid >> 2;
    const int m0   = blockIdx.y * 128;
    const int n0   = blockIdx.x * 128;
    const int lr   = lane >> 2;
    const int lc   = lane & 3;
    const int nch  = 32;

    uint32_t sbase = smem_u32(smem);

    auto ld_stage = [&](int stage, int c) {
        uint32_t sb = sbase + stage * CSTAGE_B;
        int kt = c << 5;
        int sp = kt >> 8, ko = kt & 255;
        #pragma unroll
        for (int i = 0; i < 8; i++) {
            int idx = t + i * 256;
            int pl  = idx >> 9;
            int rem = idx & 511;
            int row = rem >> 2, q = rem & 3;
            uint32_t dst = sb + pl * CPLANE_B + row * CPROW_B + q * 16;
            const __nv_bfloat16* src;
            if (pl < 2) {
                const __nv_bfloat16* P = (pl == 0) ? T0 : T1;
                int m = m0 + row;
                int g = m / 27, tp = m - g * 27;
                src = P + (size_t)((g * 30 + tp + sp) * 256 + ko) + q * 8;
            } else {
                const __nv_bfloat16* P = (pl == 2) ? W0 : W1;
                src = P + (size_t)(n0 + row) * 1024 + kt + q * 8;
            }
            cpasync16(dst, src);
        }
        asm volatile("cp.async.commit_group;" ::: "memory");
    };

    float acc[2][8][4];
    #pragma unroll
    for (int m = 0; m < 2; m++)
        #pragma unroll
        for (int j = 0; j < 8; j++)
            #pragma unroll
            for (int q = 0; q < 4; q++) acc[m][j][q] = 0.f;

    ld_stage(0, 0);
    ld_stage(1, 1);

    for (int c = 0; c < nch; c++) {
        if (c + 1 < nch) asm volatile("cp.async.wait_group 1;" ::: "memory");
        else             asm volatile("cp.async.wait_group 0;" ::: "memory");
        __syncthreads();

        const char* sb = smem + (c & 1) * CSTAGE_B;

        #pragma unroll
        for (int s = 0; s < 2; s++) {
            int kc = s * 32 + lc * 4;
            uint32_t A0f[2][4], A1f[2][4];
            #pragma unroll
            for (int m = 0; m < 2; m++) {
                int r0 = (wm * 32 + m * 16 + lr) * CPROW_B;
                int r1 = r0 + 8 * CPROW_B;
                A0f[m][0] = *(const uint32_t*)(sb + r0 + kc);
                A0f[m][1] = *(const uint32_t*)(sb + r1 + kc);
                A0f[m][2] = *(const uint32_t*)(sb + r0 + kc + 16);
                A0f[m][3] = *(const uint32_t*)(sb + r1 + kc + 16);
                A1f[m][0] = *(const uint32_t*)(sb + CPLANE_B + r0 + kc);
                A1f[m][1] = *(const uint32_t*)(sb + CPLANE_B + r1 + kc);
                A1f[m][2] = *(const uint32_t*)(sb + CPLANE_B + r0 + kc + 16);
                A1f[m][3] = *(const uint32_t*)(sb + CPLANE_B + r1 + kc + 16);
            }
            #pragma unroll
            for (int j = 0; j < 8; j++) {
                int nr = (wn * 64 + j * 8 + lr) * CPROW_B;
                uint32_t b00 = *(const uint32_t*)(sb + 2*CPLANE_B + nr + kc);
                uint32_t b01 = *(const uint32_t*)(sb + 2*CPLANE_B + nr + kc + 16);
                uint32_t b10 = *(const uint32_t*)(sb + 3*CPLANE_B + nr + kc);
                uint32_t b11 = *(const uint32_t*)(sb + 3*CPLANE_B + nr + kc + 16);
                #pragma unroll
                for (int m = 0; m < 2; m++)
                    mma16bf(acc[m][j], A0f[m][0], A0f[m][1], A0f[m][2], A0f[m][3], b00, b01);
                #pragma unroll
                for (int m = 0; m < 2; m++)
                    mma16bf(acc[m][j], A0f[m][0], A0f[m][1], A0f[m][2], A0f[m][3], b10, b11);
                #pragma unroll
                for (int m = 0; m < 2; m++)
                    mma16bf(acc[m][j], A1f[m][0], A1f[m][1], A1f[m][2], A1f[m][3], b00, b01);
            }
        }
        if (c + 2 < nch) {
            __syncthreads();
            ld_stage(c & 1, c + 2);
        }
    }

    #pragma unroll
    for (int m = 0; m < 2; m++) {
        int row = m0 + wm * 32 + m * 16 + lr;
        #pragma unroll
        for (int j = 0; j < 8; j++) {
            int col = n0 + wn * 64 + j * 8 + 2 * lc;
            float b0 = bias[col], b1 = bias[col + 1];
            float y00 = fmaxf(acc[m][j][0] + b0, 0.f);
            float y01 = fmaxf(acc[m][j][1] + b1, 0.f);
            float y10 = fmaxf(acc[m][j][2] + b0, 0.f);
            float y11 = fmaxf(acc[m][j][3] + b1, 0.f);
            __nv_bfloat162 s00 = bf2_split(y00), s01 = bf2_split(y01);
            __nv_bfloat162 s10 = bf2_split(y10), s11 = bf2_split(y11);
            size_t o0 = (size_t)row * 256 + col;
            size_t o1 = (size_t)(row + 8) * 256 + col;
            __nv_bfloat162 p;
            p.x = s00.x; p.y = s01.x; *(__nv_bfloat162*)(Y0 + o0) = p;
            p.x = s00.y; p.y = s01.y; *(__nv_bfloat162*)(Y1 + o0) = p;
            p.x = s10.x; p.y = s11.x; *(__nv_bfloat162*)(Y0 + o1) = p;
            p.x = s10.y; p.y = s11.y; *(__nv_bfloat162*)(Y1 + o1) = p;
        }
    }
}

// ============ lin1 TC GEMM (verbatim R12) ====================================
__global__ __launch_bounds__(256) void lin1_tc(
    const __nv_bfloat16* __restrict__ Y0, const __nv_bfloat16* __restrict__ Y1,
    const __nv_bfloat16* __restrict__ P0, const __nv_bfloat16* __restrict__ P1,
    float* __restrict__ Z)
{
    extern __shared__ char smem[];
    const int t    = threadIdx.x;
    const int lane = t & 31;
    const int wid  = t >> 5;
    const int wm   = wid & 3;
    const int wn   = wid >> 2;
    const int m0   = blockIdx.y * 128;
    const int n0   = blockIdx.x * 128;
    const int ts   = blockIdx.z;
    const int lr   = lane >> 2;
    const int lc   = lane & 3;
    const int nch  = 8;

    uint32_t sbase = smem_u32(smem);

    auto ld_stage = [&](int stage, int c) {
        uint32_t sb = sbase + stage * CSTAGE_B;
        int kt = c << 5;
        #pragma unroll
        for (int i = 0; i < 8; i++) {
            int idx = t + i * 256;
            int pl  = idx >> 9;
            int rem = idx & 511;
            int row = rem >> 2, q = rem & 3;
            uint32_t dst = sb + pl * CPLANE_B + row * CPROW_B + q * 16;
            const __nv_bfloat16* src;
            if (pl < 2) {
                const __nv_bfloat16* P = (pl == 0) ? Y0 : Y1;
                src = P + ((size_t)((m0 + row) * LOUT + ts)) * 256 + kt + q * 8;
            } else {
                const __nv_bfloat16* P = (pl == 2) ? P0 : P1;
                src = P + ((size_t)(ts * 256 + n0 + row)) * 256 + kt + q * 8;
            }
            cpasync16(dst, src);
        }
        asm volatile("cp.async.commit_group;" ::: "memory");
    };

    float acc[2][8][4];
    #pragma unroll
    for (int m = 0; m < 2; m++)
        #pragma unroll
        for (int j = 0; j < 8; j++)
            #pragma unroll
            for (int q = 0; q < 4; q++) acc[m][j][q] = 0.f;

    ld_stage(0, 0);
    ld_stage(1, 1);

    for (int c = 0; c < nch; c++) {
        if (c + 1 < nch) asm volatile("cp.async.wait_group 1;" ::: "memory");
        else             asm volatile("cp.async.wait_group 0;" ::: "memory");
        __syncthreads();

        const char* sb = smem + (c & 1) * CSTAGE_B;

        #pragma unroll
        for (int s = 0; s < 2; s++) {
            int kc = s * 32 + lc * 4;
            uint32_t A0f[2][4], A1f[2][4];
            #pragma unroll
            for (int m = 0; m < 2; m++) {
                int r0 = (wm * 32 + m * 16 + lr) * CPROW_B;
                int r1 = r0 + 8 * CPROW_B;
                A0f[m][0] = *(const uint32_t*)(sb + r0 + kc);
                A0f[m][1] = *(const uint32_t*)(sb + r1 + kc);
                A0f[m][2] = *(const uint32_t*)(sb + r0 + kc + 16);
                A0f[m][3] = *(const uint32_t*)(sb + r1 + kc + 16);
                A1f[m][0] = *(const uint32_t*)(sb + CPLANE_B + r0 + kc);
                A1f[m][1] = *(const uint32_t*)(sb + CPLANE_B + r1 + kc);
                A1f[m][2] = *(const uint32_t*)(sb + CPLANE_B + r0 + kc + 16);
                A1f[m][3] = *(const uint32_t*)(sb + CPLANE_B + r1 + kc + 16);
            }
            #pragma unroll
            for (int j = 0; j < 8; j++) {
                int nr = (wn * 64 + j * 8 + lr) * CPROW_B;
                uint32_t b00 = *(const uint32_t*)(sb + 2*CPLANE_B + nr + kc);
                uint32_t b01 = *(const uint32_t*)(sb + 2*CPLANE_B + nr + kc + 16);
                uint32_t b10 = *(const uint32_t*)(sb + 3*CPLANE_B + nr + kc);
                uint32_t b11 = *(const uint32_t*)(sb + 3*CPLANE_B + nr + kc + 16);
                #pragma unroll
                for (int m = 0; m < 2; m++)
                    mma16bf(acc[m][j], A0f[m][0], A0f[m][1], A0f[m][2], A0f[m][3], b00, b01);
                #pragma unroll
                for (int m = 0; m < 2; m++)
                    mma16bf(acc[m][j], A0f[m][0], A0f[m][1], A0f[m][2], A0f[m][3], b10, b11);
                #pragma unroll
                for (int m = 0; m < 2; m++)
                    mma16bf(acc[m][j], A1f[m][0], A1f[m][1], A1f[m][2], A1f[m][3], b00, b01);
            }
        }
        if (c + 2 < nch) {
            __syncthreads();
            ld_stage(c & 1, c + 2);
        }
    }

    #pragma unroll
    for (int m = 0; m < 2; m++) {
        int g = m0 + wm * 32 + m * 16 + lr;
        #pragma unroll
        for (int j = 0; j < 8; j++) {
            int col = n0 + wn * 64 + j * 8 + 2 * lc;
            atomicAdd(&Z[(size_t)g * 256 + col],           acc[m][j][0]);
            atomicAdd(&Z[(size_t)g * 256 + col + 1],       acc[m][j][1]);
            atomicAdd(&Z[(size_t)(g + 8) * 256 + col],     acc[m][j][2]);
            atomicAdd(&Z[(size_t)(g + 8) * 256 + col + 1], acc[m][j][3]);
        }
    }
}

// ------------- final MLP (verbatim) ------------------------------------------
__global__ __launch_bounds__(256) void mlp_kernel(
    const float* __restrict__ z1acc, const float* __restrict__ b1,
    const float* __restrict__ W2,   const float* __restrict__ b2,
    const float* __restrict__ W3,   const float* __restrict__ b3,
    float* __restrict__ out)
{
    int g = blockIdx.x, t = threadIdx.x;
    __shared__ float s1[256];
    __shared__ float s2[128];
    s1[t] = fmaxf(z1acc[(size_t)g * 256 + t] + b1[t], 0.f);
    __syncthreads();
    if (t < 128) {
        float acc = b2[t];
        #pragma unroll 8
        for (int k = 0; k < 256; k++) acc += s1[k] * W2[(size_t)k * 128 + t];
        s2[t] = fmaxf(acc, 0.f);
    }
    __syncthreads();
    if (t < 10) {
        float acc = b3[t];
        #pragma unroll
        for (int k = 0; k < 128; k++) acc += s2[k] * W3[(size_t)k * 10 + t];
        out[(size_t)g * 10 + t] = fmaxf(acc, 0.f);
    }
}

// ---------------- launch ----------------
extern "C" void kernel_launch(void* const* d_in, const int* in_sizes, int n_in,
                              void* d_out, int out_size)
{
    const float* x  = (const float*)d_in[0];
    const int*   ei = (const int*)  d_in[1];
    int E = in_sizes[1] / 2;
    const int* src = ei;
    const int* dst = ei + E;

    const float* wl[4] = {(const float*)d_in[3], (const float*)d_in[6],
                          (const float*)d_in[9], (const float*)d_in[12]};
    const float* wr[4] = {(const float*)d_in[4], (const float*)d_in[7],
                          (const float*)d_in[10], (const float*)d_in[13]};
    const float* sb[4] = {(const float*)d_in[5], (const float*)d_in[8],
                          (const float*)d_in[11], (const float*)d_in[14]};
    const float* convw = (const float*)d_in[15];
    const float* convb = (const float*)d_in[16];
    const float* l1w   = (const float*)d_in[17];
    const float* l1b   = (const float*)d_in[18];
    const float* l2w   = (const float*)d_in[19];
    const float* l2b   = (const float*)d_in[20];
    const float* ow    = (const float*)d_in[21];
    const float* ob    = (const float*)d_in[22];

    float *pA, *pH, *pHL, *pHR, *pZ1;
    __half *pa0, *pa1, *pb0, *pb1, *pw0, *pw1;
    __nv_bfloat16 *pt0, *pt1, *pc0, *pc1, *py0, *py1, *pl0, *pl1;
    cudaGetSymbolAddress((void**)&pA,  g_A);
    cudaGetSymbolAddress((void**)&pH,  g_H);
    cudaGetSymbolAddress((void**)&pHL, g_HL);
    cudaGetSymbolAddress((void**)&pHR, g_HR);
    cudaGetSymbolAddress((void**)&pZ1, g_z1);
    cudaGetSymbolAddress((void**)&pa0, g_a0);
    cudaGetSymbolAddress((void**)&pa1, g_a1);
    cudaGetSymbolAddress((void**)&pb0, g_b0);
    cudaGetSymbolAddress((void**)&pb1, g_b1);
    cudaGetSymbolAddress((void**)&pw0, g_w0);
    cudaGetSymbolAddress((void**)&pw1, g_w1);
    cudaGetSymbolAddress((void**)&pt0, g_t0);
    cudaGetSymbolAddress((void**)&pt1, g_t1);
    cudaGetSymbolAddress((void**)&pc0, g_c0);
    cudaGetSymbolAddress((void**)&pc1, g_c1);
    cudaGetSymbolAddress((void**)&py0, g_y0);
    cudaGetSymbolAddress((void**)&py1, g_y1);
    cudaGetSymbolAddress((void**)&pl0, g_l0);
    cudaGetSymbolAddress((void**)&pl1, g_l1);

    cudaFuncSetAttribute(gemm_sage_tc, cudaFuncAttributeMaxDynamicSharedMemorySize, GSMZ);
    cudaFuncSetAttribute(conv_tc, cudaFuncAttributeMaxDynamicSharedMemorySize, CSMZ);
    cudaFuncSetAttribute(lin1_tc, cudaFuncAttributeMaxDynamicSharedMemorySize, CSMZ);

    // preprocessing (weight splits merged into ONE launch)
    zero_f<<<(NB*PP*PP + 255)/256, 256>>>(pA, NB*PP*PP);
    build_adj<<<(E + 255)/256, 256>>>(src, dst, E, pA);
    norm_adj<<<NN/8, 256>>>(pA);
    nan_split2h<<<(NN*FF + 255)/256, 256>>>(x, pa0, pa1, NN*FF);
    zero_f<<<(NB*HH + 255)/256, 256>>>(pZ1, NB*HH);
    prep_split<<<(PREP_TOTAL + 255)/256, 256>>>(
        wl[0], wr[0], wl[1], wr[1], wl[2], wr[2], wl[3], wr[3],
        convw, l1w, pw0, pw1, pc0, pc1, pl0, pl1);

    // 4 SAGE layers — fp16 2-plane 3-product TC GEMMs + exact combine
    __half *i0 = pa0, *i1 = pa1;
    __half *o0 = pb0, *o1 = pb1;
    for (int l = 0; l < 4; l++) {
        int K = (l == 0) ? FF : HH;
        size_t f0 = (size_t)(2*l)   * HH * HH;
        size_t f1 = (size_t)(2*l+1) * HH * HH;
        gemm_sage_tc<<<dim3(8, NN/128), 256, GSMZ>>>(
            i0, i1,
            pw0+f0, pw1+f0,
            pw0+f1, pw1+f1,
            pHL, pHR, K);
        int last = (l == 3);
        sage_combine<<<NB, 256>>>(pHL, pHR, sb[l], pH, o0, o1, pA,
                                  last, !last);
        __half* tmp;
        tmp = i0; i0 = o0; o0 = tmp;
        tmp = i1; i1 = o1; o1 = tmp;
    }

    // SortPool (exact fp32 keys) -> conv1d TC -> lin1 TC -> MLP
    sort_topk2<<<NB, 256>>>(pH, pt0, pt1);
    conv_tc<<<dim3(2, MCONV/128), 256, CSMZ>>>(pt0, pt1, pc0, pc1, py0, py1, convb);
    lin1_tc<<<dim3(2, 4, LOUT), 256, CSMZ>>>(py0, py1, pl0, pl1, pZ1);
    mlp_kernel<<<NB, 256>>>(pZ1, l1b, l2w, l2b, ow, ob, (float*)d_out);
}